// round 15
// baseline (speedup 1.0000x reference)
#include <cuda_runtime.h>
#include <cuda_bf16.h>
#include <math.h>
#include <stdint.h>

typedef unsigned long long u64;
#define NROWS 1048576ull
#define NTILES 8192
#define NG 296            /* persistent grid: 2 CTAs x 148 SMs */

// ==================== device globals (no runtime alloc) ====================
__device__ float g_m1[NROWS * 64];      // m1, reused as z1
__device__ float g_m2[NROWS * 64];      // m2, reused as z2
__device__ float g_h [NROWS * 64];      // sqrt(relu(corr))
__device__ float g_part[NG * 128];      // per-CTA [sum(64)|sumsq(64)]
__device__ float g_ss1[128];            // BN1 [scale|shift]
__device__ float g_ss2[128];            // BN2
// 7 weight matrices as pre-swizzled SW128 images: [m][hi 8KB][lo 8KB]
// m: 0=w11 1=w12 2=w21 3=w22 ([n][k])  4=uW1^T k<64  5=uW1^T k>=64  6=uW2^T
__device__ __align__(16) unsigned char g_wimg[7 * 16384];

// ==================== helpers ====================
__device__ __forceinline__ uint32_t smem_u32(const void* p) {
    uint32_t a;
    asm("{ .reg .u64 t; cvta.to.shared.u64 t, %1; cvt.u32.u64 %0, t; }" : "=r"(a) : "l"(p));
    return a;
}
__device__ __forceinline__ uint32_t sw128(uint32_t b) { return b ^ ((b >> 3) & 0x70); }

__device__ __forceinline__ u64 ffma2(u64 acc, u64 a, u64 b) {
    u64 d;
    asm("fma.rn.f32x2 %0, %1, %2, %3;" : "=l"(d) : "l"(a), "l"(b), "l"(acc));
    return d;
}
__device__ __forceinline__ float2 u2f(u64 v) {
    float2 f;
    asm("mov.b64 {%0, %1}, %2;" : "=f"(f.x), "=f"(f.y) : "l"(v));
    return f;
}

__device__ __forceinline__ void split2(float2 v, uint32_t& hi, uint32_t& lo) {
    __nv_bfloat162 h2 = __float22bfloat162_rn(v);
    float2 hf = __bfloat1622float2(h2);
    __nv_bfloat162 l2 = __float22bfloat162_rn(make_float2(v.x - hf.x, v.y - hf.y));
    hi = *(uint32_t*)&h2;
    lo = *(uint32_t*)&l2;
}

__device__ __forceinline__ void cp16(float* dst_smem, const void* src) {
    uint32_t d = smem_u32(dst_smem);
    asm volatile("cp.async.cg.shared.global [%0], [%1], 16;" :: "r"(d), "l"(src));
}

// ==================== HMMA building blocks ====================
__device__ __forceinline__ void ldsm4(uint32_t addr, uint32_t r[4]) {
    asm volatile("ldmatrix.sync.aligned.m8n8.x4.shared.b16 {%0,%1,%2,%3}, [%4];"
        : "=r"(r[0]), "=r"(r[1]), "=r"(r[2]), "=r"(r[3]) : "r"(addr));
}
__device__ __forceinline__ void mma16816(float (&d)[4], const uint32_t (&a)[4],
                                         uint32_t b0, uint32_t b1) {
    asm volatile("mma.sync.aligned.m16n8k16.row.col.f32.bf16.bf16.f32 "
        "{%0,%1,%2,%3}, {%4,%5,%6,%7}, {%8,%9}, {%0,%1,%2,%3};"
        : "+f"(d[0]), "+f"(d[1]), "+f"(d[2]), "+f"(d[3])
        : "r"(a[0]), "r"(a[1]), "r"(a[2]), "r"(a[3]), "r"(b0), "r"(b1));
}

// Direct-register A fragment from a row-major [128][64] fp32 tile, split hi/lo.
// CS: use streaming (evict-first) loads for single-use data.
template<bool CS>
__device__ __forceinline__ void load_a_direct(const float* __restrict__ tile, int r0,
                                              int kc, int lane,
                                              uint32_t ah[4], uint32_t al[4]) {
    const float* p = tile + (size_t)(r0 + (lane >> 2)) * 64 + kc * 16 + (lane & 3) * 2;
    float2 v00, v01, v10, v11;
    if (CS) {
        v00 = __ldcs((const float2*)p);
        v01 = __ldcs((const float2*)(p + 8));
        v10 = __ldcs((const float2*)(p + 512));
        v11 = __ldcs((const float2*)(p + 520));
    } else {
        v00 = *(const float2*)p;
        v01 = *(const float2*)(p + 8);
        v10 = *(const float2*)(p + 512);
        v11 = *(const float2*)(p + 520);
    }
    split2(v00, ah[0], al[0]); split2(v10, ah[1], al[1]);
    split2(v01, ah[2], al[2]); split2(v11, ah[3], al[3]);
}

// Same but applies BN1-relu (scale/shift in smem ss[0..63], [64..127]); streaming loads.
__device__ __forceinline__ void load_a_bn(const float* __restrict__ tile,
                                          const float* __restrict__ sss, int r0,
                                          int kc, int lane,
                                          uint32_t ah[4], uint32_t al[4]) {
    const int c = kc * 16 + (lane & 3) * 2;
    float2 s0 = *(const float2*)(sss + c),      s8 = *(const float2*)(sss + c + 8);
    float2 h0 = *(const float2*)(sss + 64 + c), h8 = *(const float2*)(sss + 64 + c + 8);
    const float* p = tile + (size_t)(r0 + (lane >> 2)) * 64 + c;
    float2 v00 = __ldcs((const float2*)p);
    float2 v01 = __ldcs((const float2*)(p + 8));
    float2 v10 = __ldcs((const float2*)(p + 512));
    float2 v11 = __ldcs((const float2*)(p + 520));
    v00.x = fmaxf(v00.x * s0.x + h0.x, 0.f); v00.y = fmaxf(v00.y * s0.y + h0.y, 0.f);
    v10.x = fmaxf(v10.x * s0.x + h0.x, 0.f); v10.y = fmaxf(v10.y * s0.y + h0.y, 0.f);
    v01.x = fmaxf(v01.x * s8.x + h8.x, 0.f); v01.y = fmaxf(v01.y * s8.y + h8.y, 0.f);
    v11.x = fmaxf(v11.x * s8.x + h8.x, 0.f); v11.y = fmaxf(v11.y * s8.y + h8.y, 0.f);
    split2(v00, ah[0], al[0]); split2(v10, ah[1], al[1]);
    split2(v01, ah[2], al[2]); split2(v11, ah[3], al[3]);
}

// One k16 step vs B images (full n=64): Ah*Bh + Al*Bh + Ah*Bl.
__device__ __forceinline__ void mma_k16(uint32_t bH, uint32_t bL, int kc, int lane,
                                        const uint32_t (&ah)[4], const uint32_t (&al)[4],
                                        float (&acc)[8][4]) {
    const int grp = lane >> 3, li = lane & 7;
    const int brow_off = li + ((grp >> 1) << 3);
    const uint32_t cb = (uint32_t)((kc * 16 + ((grp & 1) << 3)) * 2);
#pragma unroll
    for (int n2 = 0; n2 < 4; n2++) {
        int brow = n2 * 16 + brow_off;
        uint32_t bx = (uint32_t)(brow * 128) + (cb ^ (uint32_t)((brow & 7) << 4));
        uint32_t b[4];
        ldsm4(bH + bx, b);
        mma16816(acc[n2 * 2],     ah, b[0], b[1]);
        mma16816(acc[n2 * 2 + 1], ah, b[2], b[3]);
        mma16816(acc[n2 * 2],     al, b[0], b[1]);
        mma16816(acc[n2 * 2 + 1], al, b[2], b[3]);
        ldsm4(bL + bx, b);
        mma16816(acc[n2 * 2],     ah, b[0], b[1]);
        mma16816(acc[n2 * 2 + 1], ah, b[2], b[3]);
    }
}

// Full K=64 matmul with A from an SW128 smem image.
__device__ __forceinline__ void warp_mma_k64_img(uint32_t aH, uint32_t aL,
                                                 uint32_t bH, uint32_t bL,
                                                 int r0, int lane, float (&acc)[8][4])
{
    const int grp = lane >> 3, li = lane & 7;
    const int arow = r0 + li + ((grp & 1) << 3);
    const uint32_t arbase = (uint32_t)(arow * 128);
    const uint32_t arxor = (uint32_t)((arow & 7) << 4);
    const int akhi = (grp >> 1) << 3;
#pragma unroll
    for (int kk = 0; kk < 4; kk++) {
        uint32_t acb = (uint32_t)((kk * 16 + akhi) * 2);
        uint32_t ah[4], al[4];
        ldsm4(aH + arbase + (acb ^ arxor), ah);
        ldsm4(aL + arbase + (acb ^ arxor), al);
        mma_k16(bH, bL, kk, lane, ah, al, acc);
    }
}

// epilogue: relu(acc+bias) -> split-store into smem image (warp-private rows)
__device__ __forceinline__ void epi_to_img(float (&acc)[8][4], const float* bias,
                                           char* smp, uint32_t hiOff, uint32_t loOff,
                                           int r0, int lane)
{
    const int tr = lane >> 2, tc2 = lane & 3;
    const int r1 = r0 + tr, r2 = r1 + 8;
    const uint32_t x1 = (uint32_t)((r1 & 7) << 4), x2 = (uint32_t)((r2 & 7) << 4);
#pragma unroll
    for (int nt = 0; nt < 8; nt++) {
        int c0 = nt * 8 + 2 * tc2;
        float b0 = bias[c0], b1 = bias[c0 + 1];
        uint32_t cb = (uint32_t)(c0 * 2);
        uint32_t hi, lo;
        float2 v;
        v.x = fmaxf(acc[nt][0] + b0, 0.f);
        v.y = fmaxf(acc[nt][1] + b1, 0.f);
        split2(v, hi, lo);
        *(uint32_t*)(smp + hiOff + r1 * 128 + (cb ^ x1)) = hi;
        *(uint32_t*)(smp + loOff + r1 * 128 + (cb ^ x1)) = lo;
        v.x = fmaxf(acc[nt][2] + b0, 0.f);
        v.y = fmaxf(acc[nt][3] + b1, 0.f);
        split2(v, hi, lo);
        *(uint32_t*)(smp + hiOff + r2 * 128 + (cb ^ x2)) = hi;
        *(uint32_t*)(smp + loOff + r2 * 128 + (cb ^ x2)) = lo;
    }
}

// epilogue: relu(acc+bias) -> fp32 global rows (streaming stores: read once later)
__device__ __forceinline__ void epi_to_global_relu(float (&acc)[8][4], const float* bias,
                                                   float* gdst, int r0, int lane)
{
    const int tr = lane >> 2, tc2 = lane & 3;
    const int r1 = r0 + tr, r2 = r1 + 8;
#pragma unroll
    for (int nt = 0; nt < 8; nt++) {
        int c0 = nt * 8 + 2 * tc2;
        float b0 = bias[c0], b1 = bias[c0 + 1];
        __stcs((float2*)(gdst + (size_t)r1 * 64 + c0),
               make_float2(fmaxf(acc[nt][0] + b0, 0.f), fmaxf(acc[nt][1] + b1, 0.f)));
        __stcs((float2*)(gdst + (size_t)r2 * 64 + c0),
               make_float2(fmaxf(acc[nt][2] + b0, 0.f), fmaxf(acc[nt][3] + b1, 0.f)));
    }
}

// epilogue: z=acc+bias -> global (streaming) + warp shuffle-reduced stats
__device__ __forceinline__ void epi_stats(float (&acc)[8][4], const float* bias,
                                          float* gdst, int r0, int lane,
                                          float* red_s, float* red_q, int w)
{
    const int tr = lane >> 2, tc2 = lane & 3;
    const int r1 = r0 + tr, r2 = r1 + 8;
#pragma unroll
    for (int nt = 0; nt < 8; nt++) {
        int c0 = nt * 8 + 2 * tc2;
        float b0 = bias[c0], b1 = bias[c0 + 1];
        float z00 = acc[nt][0] + b0, z01 = acc[nt][1] + b1;
        float z10 = acc[nt][2] + b0, z11 = acc[nt][3] + b1;
        __stcs((float2*)(gdst + (size_t)r1 * 64 + c0), make_float2(z00, z01));
        __stcs((float2*)(gdst + (size_t)r2 * 64 + c0), make_float2(z10, z11));
        float s0 = z00 + z10, s1 = z01 + z11;
        float q0 = z00 * z00 + z10 * z10, q1 = z01 * z01 + z11 * z11;
#pragma unroll
        for (int m = 4; m < 32; m <<= 1) {
            s0 += __shfl_xor_sync(0xffffffffu, s0, m);
            s1 += __shfl_xor_sync(0xffffffffu, s1, m);
            q0 += __shfl_xor_sync(0xffffffffu, q0, m);
            q1 += __shfl_xor_sync(0xffffffffu, q1, m);
        }
        if (tr == 0) {
            red_s[w * 64 + c0]     = s0;
            red_s[w * 64 + c0 + 1] = s1;
            red_q[w * 64 + c0]     = q0;
            red_q[w * 64 + c0 + 1] = q1;
        }
    }
}

// ==================== prep: weights -> bf16 hi/lo SW128 images (parallel) ====================
__global__ void prep_kernel(const float* __restrict__ w11, const float* __restrict__ w12,
                            const float* __restrict__ w21, const float* __restrict__ w22,
                            const float* __restrict__ uW1, const float* __restrict__ uW2)
{
    int idx = blockIdx.x * 256 + threadIdx.x;
    if (idx >= 7 * 4096) return;
    int m = idx >> 12, e = idx & 4095, n = e >> 6, k = e & 63;
    float v;
    if      (m == 0) v = w11[e];
    else if (m == 1) v = w12[e];
    else if (m == 2) v = w21[e];
    else if (m == 3) v = w22[e];
    else if (m == 4) v = uW1[k * 64 + n];
    else if (m == 5) v = uW1[(64 + k) * 64 + n];
    else             v = uW2[k * 64 + n];
    __nv_bfloat16 hi = __float2bfloat16(v);
    __nv_bfloat16 lo = __float2bfloat16(v - __bfloat162float(hi));
    uint32_t sw = sw128((uint32_t)(n * 128 + k * 2));
    *(__nv_bfloat16*)(g_wimg + m * 16384 + sw)        = hi;
    *(__nv_bfloat16*)(g_wimg + m * 16384 + 8192 + sw) = lo;
}

// ==================== K1: fused 4-layer MLP pair, shared-A dual layer1 ====================
#define MLP_HH 0u
#define MLP_HL 16384u
#define MLP_W  32768u       /* 4 x 16KB images */
#define MLP_BIAS 98304u     /* 256 floats */
#define MLP_SMEM 99328

__global__ void __launch_bounds__(256, 2) mlp_mma_kernel(const float* __restrict__ x,
    const float* __restrict__ b11, const float* __restrict__ b12,
    const float* __restrict__ b21, const float* __restrict__ b22)
{
    extern __shared__ __align__(16) char smp[];
    const uint32_t sb = smem_u32(smp);
    const int t = threadIdx.x;
    const int w = t >> 5, lane = t & 31;
    const int r0 = w * 16;

    {
        const uint4* src = (const uint4*)g_wimg;
        uint4* dst = (uint4*)(smp + MLP_W);
        for (int i = t; i < 4096; i += 256) dst[i] = src[i];
    }
    float* sbias = (float*)(smp + MLP_BIAS);
    if (t < 64) {
        sbias[t]       = b11[t];
        sbias[64 + t]  = b12[t];
        sbias[128 + t] = b21[t];
        sbias[192 + t] = b22[t];
    }
    __syncthreads();

    for (int tile = blockIdx.x; tile < NTILES; tile += gridDim.x) {
        const size_t base = (size_t)tile * 8192;
        float acc1[8][4], acc2[8][4], acc[8][4];
        uint32_t ah[4], al[4];

        // ---- layer1 of BOTH MLPs: x loaded+split ONCE, two accumulator sets ----
#pragma unroll
        for (int i = 0; i < 8; i++) {
            acc1[i][0]=acc1[i][1]=acc1[i][2]=acc1[i][3]=0.f;
            acc2[i][0]=acc2[i][1]=acc2[i][2]=acc2[i][3]=0.f;
        }
#pragma unroll
        for (int kc = 0; kc < 4; kc++) {
            load_a_direct<false>(x + base, r0, kc, lane, ah, al);
            mma_k16(sb + MLP_W + 0 * 16384, sb + MLP_W + 0 * 16384 + 8192, kc, lane, ah, al, acc1);
            mma_k16(sb + MLP_W + 2 * 16384, sb + MLP_W + 2 * 16384 + 8192, kc, lane, ah, al, acc2);
        }
        // ---- MLP1: h1 image -> layer2 -> g_m1 ----
        epi_to_img(acc1, sbias + 0, smp, MLP_HH, MLP_HL, r0, lane);
        __syncwarp();
#pragma unroll
        for (int i = 0; i < 8; i++) { acc[i][0]=acc[i][1]=acc[i][2]=acc[i][3]=0.f; }
        warp_mma_k64_img(sb + MLP_HH, sb + MLP_HL,
                         sb + MLP_W + 1 * 16384, sb + MLP_W + 1 * 16384 + 8192, r0, lane, acc);
        epi_to_global_relu(acc, sbias + 64, g_m1 + base, r0, lane);
        __syncwarp();
        // ---- MLP2: h2 image (overwrite) -> layer2 -> g_m2 ----
        epi_to_img(acc2, sbias + 128, smp, MLP_HH, MLP_HL, r0, lane);
        __syncwarp();
#pragma unroll
        for (int i = 0; i < 8; i++) { acc[i][0]=acc[i][1]=acc[i][2]=acc[i][3]=0.f; }
        warp_mma_k64_img(sb + MLP_HH, sb + MLP_HL,
                         sb + MLP_W + 3 * 16384, sb + MLP_W + 3 * 16384 + 8192, r0, lane, acc);
        epi_to_global_relu(acc, sbias + 192, g_m2 + base, r0, lane);
        __syncwarp();
    }
}

// ==================== K2: corr + sqrt(relu), cp.async, chunk=4k double-buffered ====================
#define CORR_SMEM 147456

__global__ void __launch_bounds__(512, 1) corr_kernel()
{
    extern __shared__ float sm[];
    float* m1b = sm;          // buf stride 2048 floats: [8ii][4kk][64c]
    float* m2b = sm + 4096;   // buf stride 16384 floats: [4kk][64j][64c]
    const int t  = threadIdx.x;
    const int b  = blockIdx.x >> 3;
    const int i0 = (blockIdx.x & 7) * 8;
    const int cp = t & 31;
    const int jg = t >> 5;
    const float* M1 = g_m1 + (size_t)b * 262144 + (size_t)i0 * 4096;
    const float* M2 = g_m2 + (size_t)b * 262144;

    u64 acc[8][4];
#pragma unroll
    for (int ii = 0; ii < 8; ii++)
#pragma unroll
        for (int jj = 0; jj < 4; jj++) acc[ii][jj] = 0ull;

    auto stage = [&](int ch) {
        const int k0 = ch * 4;
        const int buf = ch & 1;
        const float* m2src = M2 + (size_t)k0 * 4096;
        float* m2dst = m2b + buf * 16384;
        for (int i = t; i < 4096; i += 512)
            cp16(m2dst + i * 4, m2src + i * 4);
        {
            int ii = t >> 6;
            int kk = (t >> 4) & 3;
            int c4 = t & 15;
            cp16(m1b + buf * 2048 + ii * 256 + kk * 64 + c4 * 4,
                 M1 + (size_t)ii * 4096 + (size_t)(k0 + kk) * 64 + c4 * 4);
        }
        asm volatile("cp.async.commit_group;" ::: "memory");
    };

    stage(0);
    for (int ch = 0; ch < 16; ch++) {
        if (ch < 15) {
            stage(ch + 1);
            asm volatile("cp.async.wait_group 1;" ::: "memory");
        } else {
            asm volatile("cp.async.wait_group 0;" ::: "memory");
        }
        __syncthreads();
        const int buf = ch & 1;
#pragma unroll
        for (int kk = 0; kk < 4; kk++) {
            u64 a1[8];
#pragma unroll
            for (int ii = 0; ii < 8; ii++)
                a1[ii] = *(const u64*)(m1b + buf * 2048 + ii * 256 + kk * 64 + 2 * cp);
#pragma unroll
            for (int jj = 0; jj < 4; jj++) {
                u64 v = *(const u64*)(m2b + buf * 16384 + kk * 4096 + (jg * 4 + jj) * 64 + 2 * cp);
#pragma unroll
                for (int ii = 0; ii < 8; ii++) acc[ii][jj] = ffma2(acc[ii][jj], a1[ii], v);
            }
        }
        __syncthreads();
    }

    float* H = g_h + (size_t)b * 262144 + (size_t)i0 * 4096;
#pragma unroll
    for (int ii = 0; ii < 8; ii++)
#pragma unroll
        for (int jj = 0; jj < 4; jj++) {
            float2 p = u2f(acc[ii][jj]);
            float2 o;
            o.x = sqrtf(fmaxf(p.x, 0.f));
            o.y = sqrtf(fmaxf(p.y, 0.f));
            __stcs((float2*)(H + (size_t)(ii * 64 + jg * 4 + jj) * 64 + 2 * cp), o);
        }
}

// ==================== K3: z1 = [x,h] @ uW1 + ub1, persistent + stats ====================
#define G1_W    0u          /* m4 at 0, m5 at 16384 */
#define G1_REDS 32768u
#define G1_REDQ 34816u
#define G1_BIAS 36864u
#define G1_SMEM 37120

__global__ void __launch_bounds__(256, 2) gemm1_mma_kernel(const float* __restrict__ x,
                                                           const float* __restrict__ ub1)
{
    extern __shared__ __align__(16) char smp[];
    const uint32_t sb = smem_u32(smp);
    const int t = threadIdx.x;
    const int w = t >> 5, lane = t & 31;
    const int r0 = w * 16;
    float* red_s = (float*)(smp + G1_REDS);
    float* red_q = (float*)(smp + G1_REDQ);
    float* sbias = (float*)(smp + G1_BIAS);

    {
        const uint4* src = (const uint4*)(g_wimg + 4 * 16384);
        uint4* dst = (uint4*)smp;
        for (int i = t; i < 2048; i += 256) dst[i] = src[i];
    }
    if (t < 64) sbias[t] = ub1[t];
    __syncthreads();

    float s_run = 0.f, q_run = 0.f;

    for (int tile = blockIdx.x; tile < NTILES; tile += gridDim.x) {
        const size_t base = (size_t)tile * 8192;
        float acc[8][4];
        uint32_t ah[4], al[4];
#pragma unroll
        for (int i = 0; i < 8; i++) { acc[i][0]=acc[i][1]=acc[i][2]=acc[i][3]=0.f; }
#pragma unroll
        for (int kc = 0; kc < 4; kc++) {
            load_a_direct<true>(x + base, r0, kc, lane, ah, al);
            mma_k16(sb + G1_W, sb + G1_W + 8192, kc, lane, ah, al, acc);
        }
#pragma unroll
        for (int kc = 0; kc < 4; kc++) {
            load_a_direct<true>(g_h + base, r0, kc, lane, ah, al);
            mma_k16(sb + G1_W + 16384, sb + G1_W + 16384 + 8192, kc, lane, ah, al, acc);
        }
        epi_stats(acc, sbias, g_m1 + base, r0, lane, red_s, red_q, w);
        __syncthreads();
        if (t < 64) {
            float s = 0.f, q = 0.f;
#pragma unroll
            for (int ww = 0; ww < 8; ww++) { s += red_s[ww * 64 + t]; q += red_q[ww * 64 + t]; }
            s_run += s; q_run += q;
        }
        __syncthreads();
    }
    if (t < 64) {
        g_part[(size_t)blockIdx.x * 128 + t]      = s_run;
        g_part[(size_t)blockIdx.x * 128 + 64 + t] = q_run;
    }
}

// ==================== finalize: parallel (64 CTAs, 1 channel each) ====================
__global__ void __launch_bounds__(256) finalize_kernel(const float* __restrict__ g,
                                                       const float* __restrict__ be,
                                                       float* __restrict__ ss, int count)
{
    __shared__ double reds[256], redq[256];
    const int c = blockIdx.x;          // channel 0..63
    const int t = threadIdx.x;
    double s = 0.0, q = 0.0;
    for (int i = t; i < count; i += 256) {
        s += (double)g_part[(size_t)i * 128 + c];
        q += (double)g_part[(size_t)i * 128 + 64 + c];
    }
    reds[t] = s; redq[t] = q;
    __syncthreads();
#pragma unroll
    for (int step = 128; step > 0; step >>= 1) {
        if (t < step) { reds[t] += reds[t + step]; redq[t] += redq[t + step]; }
        __syncthreads();
    }
    if (t == 0) {
        double mu  = reds[0] / (double)NROWS;
        double var = redq[0] / (double)NROWS - mu * mu;
        float sc = g[c] * rsqrtf((float)var + 1e-5f);
        ss[c]      = sc;
        ss[64 + c] = be[c] - (float)mu * sc;
    }
}

// ==================== K5: z2 = BN1relu(z1) @ uW2 + ub2, persistent + stats ====================
#define G2_W    0u
#define G2_REDS 16384u
#define G2_REDQ 18432u
#define G2_BIAS 20480u
#define G2_SS   20736u
#define G2_SMEM 21248

__global__ void __launch_bounds__(256, 2) gemm2_mma_kernel(const float* __restrict__ ub2)
{
    extern __shared__ __align__(16) char smp[];
    const uint32_t sb = smem_u32(smp);
    const int t = threadIdx.x;
    const int w = t >> 5, lane = t & 31;
    const int r0 = w * 16;
    float* red_s = (float*)(smp + G2_REDS);
    float* red_q = (float*)(smp + G2_REDQ);
    float* sbias = (float*)(smp + G2_BIAS);
    float* ss    = (float*)(smp + G2_SS);

    {
        const uint4* src = (const uint4*)(g_wimg + 6 * 16384);
        uint4* dst = (uint4*)smp;
        for (int i = t; i < 1024; i += 256) dst[i] = src[i];
    }
    if (t < 64) sbias[t] = ub2[t];
    if (t < 128) ss[t] = g_ss1[t];
    __syncthreads();

    float s_run = 0.f, q_run = 0.f;

    for (int tile = blockIdx.x; tile < NTILES; tile += gridDim.x) {
        const size_t base = (size_t)tile * 8192;
        float acc[8][4];
        uint32_t ah[4], al[4];
#pragma unroll
        for (int i = 0; i < 8; i++) { acc[i][0]=acc[i][1]=acc[i][2]=acc[i][3]=0.f; }
#pragma unroll
        for (int kc = 0; kc < 4; kc++) {
            load_a_bn(g_m1 + base, ss, r0, kc, lane, ah, al);
            mma_k16(sb + G2_W, sb + G2_W + 8192, kc, lane, ah, al, acc);
        }
        epi_stats(acc, sbias, g_m2 + base, r0, lane, red_s, red_q, w);
        __syncthreads();
        if (t < 64) {
            float s = 0.f, q = 0.f;
#pragma unroll
            for (int ww = 0; ww < 8; ww++) { s += red_s[ww * 64 + t]; q += red_q[ww * 64 + t]; }
            s_run += s; q_run += q;
        }
        __syncthreads();
    }
    if (t < 64) {
        g_part[(size_t)blockIdx.x * 128 + t]      = s_run;
        g_part[(size_t)blockIdx.x * 128 + 64 + t] = q_run;
    }
}

// ==================== K7: out = BN2relu(z2) + x (streaming) ====================
__global__ void __launch_bounds__(256) final_kernel(const float* __restrict__ x,
                                                    float* __restrict__ out)
{
    __shared__ float ss[128];
    if (threadIdx.x < 128) ss[threadIdx.x] = g_ss2[threadIdx.x];
    __syncthreads();
    const size_t total4 = NROWS * 64 / 4;
    for (size_t v = (size_t)blockIdx.x * 256 + threadIdx.x; v < total4;
         v += (size_t)gridDim.x * 256) {
        int c0 = ((int)(v & 15)) * 4;
        float4 z  = __ldcs((const float4*)((const float*)g_m2 + v * 4));
        float4 xv = __ldcs((const float4*)(x + v * 4));
        float4 o;
        o.x = fmaxf(z.x * ss[c0 + 0] + ss[64 + c0 + 0], 0.f) + xv.x;
        o.y = fmaxf(z.y * ss[c0 + 1] + ss[64 + c0 + 1], 0.f) + xv.y;
        o.z = fmaxf(z.z * ss[c0 + 2] + ss[64 + c0 + 2], 0.f) + xv.z;
        o.w = fmaxf(z.w * ss[c0 + 3] + ss[64 + c0 + 3], 0.f) + xv.w;
        __stcs((float4*)(out + v * 4), o);
    }
}

// ==================== host ====================
extern "C" void kernel_launch(void* const* d_in, const int* in_sizes, int n_in,
                              void* d_out, int out_size)
{
    const float* x    = (const float*)d_in[0];
    const float* w11  = (const float*)d_in[1];
    const float* b11  = (const float*)d_in[2];
    const float* w12  = (const float*)d_in[3];
    const float* b12  = (const float*)d_in[4];
    const float* w21  = (const float*)d_in[5];
    const float* b21  = (const float*)d_in[6];
    const float* w22  = (const float*)d_in[7];
    const float* b22  = (const float*)d_in[8];
    const float* uW1  = (const float*)d_in[9];
    const float* ub1  = (const float*)d_in[10];
    const float* g1   = (const float*)d_in[11];
    const float* be1  = (const float*)d_in[12];
    const float* uW2  = (const float*)d_in[13];
    const float* ub2  = (const float*)d_in[14];
    const float* g2   = (const float*)d_in[15];
    const float* be2  = (const float*)d_in[16];
    float* out = (float*)d_out;

    float *ss1, *ss2;
    cudaGetSymbolAddress((void**)&ss1, g_ss1);
    cudaGetSymbolAddress((void**)&ss2, g_ss2);

    cudaFuncSetAttribute(mlp_mma_kernel,   cudaFuncAttributeMaxDynamicSharedMemorySize, MLP_SMEM);
    cudaFuncSetAttribute(corr_kernel,      cudaFuncAttributeMaxDynamicSharedMemorySize, CORR_SMEM);
    cudaFuncSetAttribute(gemm1_mma_kernel, cudaFuncAttributeMaxDynamicSharedMemorySize, G1_SMEM);
    cudaFuncSetAttribute(gemm2_mma_kernel, cudaFuncAttributeMaxDynamicSharedMemorySize, G2_SMEM);

    prep_kernel<<<112, 256>>>(w11, w12, w21, w22, uW1, uW2);
    mlp_mma_kernel<<<NG, 256, MLP_SMEM>>>(x, b11, b12, b21, b22);
    corr_kernel<<<2048, 512, CORR_SMEM>>>();
    gemm1_mma_kernel<<<NG, 256, G1_SMEM>>>(x, ub1);
    finalize_kernel<<<64, 256>>>(g1, be1, ss1, NG);
    gemm2_mma_kernel<<<NG, 256, G2_SMEM>>>(ub2);
    finalize_kernel<<<64, 256>>>(g2, be2, ss2, NG);
    final_kernel<<<16384, 256>>>(x, out);
}

// round 16
// speedup vs baseline: 1.0118x; 1.0118x over previous
#include <cuda_runtime.h>
#include <cuda_bf16.h>
#include <math.h>
#include <stdint.h>

typedef unsigned long long u64;
#define NROWS 1048576ull
#define NTILES 8192
#define NG 296            /* persistent grid: 2 CTAs x 148 SMs */

// ==================== device globals (no runtime alloc) ====================
__device__ float g_m1[NROWS * 64];      // m1, reused as z1
__device__ float g_m2[NROWS * 64];      // m2, reused as z2
__device__ float g_h [NROWS * 64];      // sqrt(relu(corr))
__device__ float g_part[NG * 128];      // per-CTA [sum(64)|sumsq(64)]
__device__ float g_ss1[128];            // BN1 [scale|shift]
__device__ float g_ss2[128];            // BN2
// 7 weight matrices as pre-swizzled SW128 images: [m][hi 8KB][lo 8KB]
// m: 0=w11 1=w12 2=w21 3=w22 ([n][k])  4=uW1^T k<64  5=uW1^T k>=64  6=uW2^T
__device__ __align__(16) unsigned char g_wimg[7 * 16384];

// ==================== helpers ====================
__device__ __forceinline__ uint32_t smem_u32(const void* p) {
    uint32_t a;
    asm("{ .reg .u64 t; cvta.to.shared.u64 t, %1; cvt.u32.u64 %0, t; }" : "=r"(a) : "l"(p));
    return a;
}
__device__ __forceinline__ uint32_t sw128(uint32_t b) { return b ^ ((b >> 3) & 0x70); }

__device__ __forceinline__ u64 ffma2(u64 acc, u64 a, u64 b) {
    u64 d;
    asm("fma.rn.f32x2 %0, %1, %2, %3;" : "=l"(d) : "l"(a), "l"(b), "l"(acc));
    return d;
}
__device__ __forceinline__ float2 u2f(u64 v) {
    float2 f;
    asm("mov.b64 {%0, %1}, %2;" : "=f"(f.x), "=f"(f.y) : "l"(v));
    return f;
}

__device__ __forceinline__ void split2(float2 v, uint32_t& hi, uint32_t& lo) {
    __nv_bfloat162 h2 = __float22bfloat162_rn(v);
    float2 hf = __bfloat1622float2(h2);
    __nv_bfloat162 l2 = __float22bfloat162_rn(make_float2(v.x - hf.x, v.y - hf.y));
    hi = *(uint32_t*)&h2;
    lo = *(uint32_t*)&l2;
}

__device__ __forceinline__ void cp16(float* dst_smem, const void* src) {
    uint32_t d = smem_u32(dst_smem);
    asm volatile("cp.async.cg.shared.global [%0], [%1], 16;" :: "r"(d), "l"(src));
}

// ==================== HMMA building blocks ====================
__device__ __forceinline__ void ldsm4(uint32_t addr, uint32_t r[4]) {
    asm volatile("ldmatrix.sync.aligned.m8n8.x4.shared.b16 {%0,%1,%2,%3}, [%4];"
        : "=r"(r[0]), "=r"(r[1]), "=r"(r[2]), "=r"(r[3]) : "r"(addr));
}
__device__ __forceinline__ void mma16816(float (&d)[4], const uint32_t (&a)[4],
                                         uint32_t b0, uint32_t b1) {
    asm volatile("mma.sync.aligned.m16n8k16.row.col.f32.bf16.bf16.f32 "
        "{%0,%1,%2,%3}, {%4,%5,%6,%7}, {%8,%9}, {%0,%1,%2,%3};"
        : "+f"(d[0]), "+f"(d[1]), "+f"(d[2]), "+f"(d[3])
        : "r"(a[0]), "r"(a[1]), "r"(a[2]), "r"(a[3]), "r"(b0), "r"(b1));
}

// Direct-register A fragment from a row-major [128][64] fp32 tile, split hi/lo.
__device__ __forceinline__ void load_a_direct(const float* __restrict__ tile, int r0,
                                              int kc, int lane,
                                              uint32_t ah[4], uint32_t al[4]) {
    const float* p = tile + (size_t)(r0 + (lane >> 2)) * 64 + kc * 16 + (lane & 3) * 2;
    float2 v00 = *(const float2*)p;
    float2 v01 = *(const float2*)(p + 8);
    float2 v10 = *(const float2*)(p + 512);
    float2 v11 = *(const float2*)(p + 520);
    split2(v00, ah[0], al[0]); split2(v10, ah[1], al[1]);
    split2(v01, ah[2], al[2]); split2(v11, ah[3], al[3]);
}

// Same but applies BN1-relu (scale/shift in smem ss[0..63], [64..127]).
__device__ __forceinline__ void load_a_bn(const float* __restrict__ tile,
                                          const float* __restrict__ sss, int r0,
                                          int kc, int lane,
                                          uint32_t ah[4], uint32_t al[4]) {
    const int c = kc * 16 + (lane & 3) * 2;
    float2 s0 = *(const float2*)(sss + c),      s8 = *(const float2*)(sss + c + 8);
    float2 h0 = *(const float2*)(sss + 64 + c), h8 = *(const float2*)(sss + 64 + c + 8);
    const float* p = tile + (size_t)(r0 + (lane >> 2)) * 64 + c;
    float2 v00 = *(const float2*)p;
    float2 v01 = *(const float2*)(p + 8);
    float2 v10 = *(const float2*)(p + 512);
    float2 v11 = *(const float2*)(p + 520);
    v00.x = fmaxf(v00.x * s0.x + h0.x, 0.f); v00.y = fmaxf(v00.y * s0.y + h0.y, 0.f);
    v10.x = fmaxf(v10.x * s0.x + h0.x, 0.f); v10.y = fmaxf(v10.y * s0.y + h0.y, 0.f);
    v01.x = fmaxf(v01.x * s8.x + h8.x, 0.f); v01.y = fmaxf(v01.y * s8.y + h8.y, 0.f);
    v11.x = fmaxf(v11.x * s8.x + h8.x, 0.f); v11.y = fmaxf(v11.y * s8.y + h8.y, 0.f);
    split2(v00, ah[0], al[0]); split2(v10, ah[1], al[1]);
    split2(v01, ah[2], al[2]); split2(v11, ah[3], al[3]);
}

// One k16 step vs B images (full n=64): Ah*Bh + Al*Bh + Ah*Bl.
__device__ __forceinline__ void mma_k16(uint32_t bH, uint32_t bL, int kc, int lane,
                                        const uint32_t (&ah)[4], const uint32_t (&al)[4],
                                        float (&acc)[8][4]) {
    const int grp = lane >> 3, li = lane & 7;
    const int brow_off = li + ((grp >> 1) << 3);
    const uint32_t cb = (uint32_t)((kc * 16 + ((grp & 1) << 3)) * 2);
#pragma unroll
    for (int n2 = 0; n2 < 4; n2++) {
        int brow = n2 * 16 + brow_off;
        uint32_t bx = (uint32_t)(brow * 128) + (cb ^ (uint32_t)((brow & 7) << 4));
        uint32_t b[4];
        ldsm4(bH + bx, b);
        mma16816(acc[n2 * 2],     ah, b[0], b[1]);
        mma16816(acc[n2 * 2 + 1], ah, b[2], b[3]);
        mma16816(acc[n2 * 2],     al, b[0], b[1]);
        mma16816(acc[n2 * 2 + 1], al, b[2], b[3]);
        ldsm4(bL + bx, b);
        mma16816(acc[n2 * 2],     ah, b[0], b[1]);
        mma16816(acc[n2 * 2 + 1], ah, b[2], b[3]);
    }
}

// Full K=64 matmul with A from an SW128 smem image.
__device__ __forceinline__ void warp_mma_k64_img(uint32_t aH, uint32_t aL,
                                                 uint32_t bH, uint32_t bL,
                                                 int r0, int lane, float (&acc)[8][4])
{
    const int grp = lane >> 3, li = lane & 7;
    const int arow = r0 + li + ((grp & 1) << 3);
    const uint32_t arbase = (uint32_t)(arow * 128);
    const uint32_t arxor = (uint32_t)((arow & 7) << 4);
    const int akhi = (grp >> 1) << 3;
#pragma unroll
    for (int kk = 0; kk < 4; kk++) {
        uint32_t acb = (uint32_t)((kk * 16 + akhi) * 2);
        uint32_t ah[4], al[4];
        ldsm4(aH + arbase + (acb ^ arxor), ah);
        ldsm4(aL + arbase + (acb ^ arxor), al);
        mma_k16(bH, bL, kk, lane, ah, al, acc);
    }
}

// epilogue: relu(acc+bias) -> split-store into smem image (warp-private rows)
__device__ __forceinline__ void epi_to_img(float (&acc)[8][4], const float* bias,
                                           char* smp, uint32_t hiOff, uint32_t loOff,
                                           int r0, int lane)
{
    const int tr = lane >> 2, tc2 = lane & 3;
    const int r1 = r0 + tr, r2 = r1 + 8;
    const uint32_t x1 = (uint32_t)((r1 & 7) << 4), x2 = (uint32_t)((r2 & 7) << 4);
#pragma unroll
    for (int nt = 0; nt < 8; nt++) {
        int c0 = nt * 8 + 2 * tc2;
        float b0 = bias[c0], b1 = bias[c0 + 1];
        uint32_t cb = (uint32_t)(c0 * 2);
        uint32_t hi, lo;
        float2 v;
        v.x = fmaxf(acc[nt][0] + b0, 0.f);
        v.y = fmaxf(acc[nt][1] + b1, 0.f);
        split2(v, hi, lo);
        *(uint32_t*)(smp + hiOff + r1 * 128 + (cb ^ x1)) = hi;
        *(uint32_t*)(smp + loOff + r1 * 128 + (cb ^ x1)) = lo;
        v.x = fmaxf(acc[nt][2] + b0, 0.f);
        v.y = fmaxf(acc[nt][3] + b1, 0.f);
        split2(v, hi, lo);
        *(uint32_t*)(smp + hiOff + r2 * 128 + (cb ^ x2)) = hi;
        *(uint32_t*)(smp + loOff + r2 * 128 + (cb ^ x2)) = lo;
    }
}

// epilogue: relu(acc+bias) -> fp32 global rows
__device__ __forceinline__ void epi_to_global_relu(float (&acc)[8][4], const float* bias,
                                                   float* gdst, int r0, int lane)
{
    const int tr = lane >> 2, tc2 = lane & 3;
    const int r1 = r0 + tr, r2 = r1 + 8;
#pragma unroll
    for (int nt = 0; nt < 8; nt++) {
        int c0 = nt * 8 + 2 * tc2;
        float b0 = bias[c0], b1 = bias[c0 + 1];
        *(float2*)(gdst + (size_t)r1 * 64 + c0) =
            make_float2(fmaxf(acc[nt][0] + b0, 0.f), fmaxf(acc[nt][1] + b1, 0.f));
        *(float2*)(gdst + (size_t)r2 * 64 + c0) =
            make_float2(fmaxf(acc[nt][2] + b0, 0.f), fmaxf(acc[nt][3] + b1, 0.f));
    }
}

// epilogue: z=acc+bias -> global + warp shuffle-reduced sum/sumsq into red buffers
__device__ __forceinline__ void epi_stats(float (&acc)[8][4], const float* bias,
                                          float* gdst, int r0, int lane,
                                          float* red_s, float* red_q, int w)
{
    const int tr = lane >> 2, tc2 = lane & 3;
    const int r1 = r0 + tr, r2 = r1 + 8;
#pragma unroll
    for (int nt = 0; nt < 8; nt++) {
        int c0 = nt * 8 + 2 * tc2;
        float b0 = bias[c0], b1 = bias[c0 + 1];
        float z00 = acc[nt][0] + b0, z01 = acc[nt][1] + b1;
        float z10 = acc[nt][2] + b0, z11 = acc[nt][3] + b1;
        *(float2*)(gdst + (size_t)r1 * 64 + c0) = make_float2(z00, z01);
        *(float2*)(gdst + (size_t)r2 * 64 + c0) = make_float2(z10, z11);
        float s0 = z00 + z10, s1 = z01 + z11;
        float q0 = z00 * z00 + z10 * z10, q1 = z01 * z01 + z11 * z11;
#pragma unroll
        for (int m = 4; m < 32; m <<= 1) {
            s0 += __shfl_xor_sync(0xffffffffu, s0, m);
            s1 += __shfl_xor_sync(0xffffffffu, s1, m);
            q0 += __shfl_xor_sync(0xffffffffu, q0, m);
            q1 += __shfl_xor_sync(0xffffffffu, q1, m);
        }
        if (tr == 0) {
            red_s[w * 64 + c0]     = s0;
            red_s[w * 64 + c0 + 1] = s1;
            red_q[w * 64 + c0]     = q0;
            red_q[w * 64 + c0 + 1] = q1;
        }
    }
}

// ==================== prep: weights -> bf16 hi/lo SW128 images (parallel) ====================
__global__ void prep_kernel(const float* __restrict__ w11, const float* __restrict__ w12,
                            const float* __restrict__ w21, const float* __restrict__ w22,
                            const float* __restrict__ uW1, const float* __restrict__ uW2)
{
    int idx = blockIdx.x * 256 + threadIdx.x;
    if (idx >= 7 * 4096) return;
    int m = idx >> 12, e = idx & 4095, n = e >> 6, k = e & 63;
    float v;
    if      (m == 0) v = w11[e];
    else if (m == 1) v = w12[e];
    else if (m == 2) v = w21[e];
    else if (m == 3) v = w22[e];
    else if (m == 4) v = uW1[k * 64 + n];
    else if (m == 5) v = uW1[(64 + k) * 64 + n];
    else             v = uW2[k * 64 + n];
    __nv_bfloat16 hi = __float2bfloat16(v);
    __nv_bfloat16 lo = __float2bfloat16(v - __bfloat162float(hi));
    uint32_t sw = sw128((uint32_t)(n * 128 + k * 2));
    *(__nv_bfloat16*)(g_wimg + m * 16384 + sw)        = hi;
    *(__nv_bfloat16*)(g_wimg + m * 16384 + 8192 + sw) = lo;
}

// ==================== K1: fused 4-layer MLP pair, persistent multi-tile ====================
#define MLP_HH 0u
#define MLP_HL 16384u
#define MLP_W  32768u       /* 4 x 16KB images */
#define MLP_BIAS 98304u     /* 256 floats */
#define MLP_SMEM 99328

__global__ void __launch_bounds__(256, 2) mlp_mma_kernel(const float* __restrict__ x,
    const float* __restrict__ b11, const float* __restrict__ b12,
    const float* __restrict__ b21, const float* __restrict__ b22)
{
    extern __shared__ __align__(16) char smp[];
    const uint32_t sb = smem_u32(smp);
    const int t = threadIdx.x;
    const int w = t >> 5, lane = t & 31;
    const int r0 = w * 16;

    {
        const uint4* src = (const uint4*)g_wimg;
        uint4* dst = (uint4*)(smp + MLP_W);
        for (int i = t; i < 4096; i += 256) dst[i] = src[i];
    }
    float* sbias = (float*)(smp + MLP_BIAS);
    if (t < 64) {
        sbias[t]       = b11[t];
        sbias[64 + t]  = b12[t];
        sbias[128 + t] = b21[t];
        sbias[192 + t] = b22[t];
    }
    __syncthreads();

    for (int tile = blockIdx.x; tile < NTILES; tile += gridDim.x) {
        const size_t base = (size_t)tile * 8192;
        float acc[8][4];
        uint32_t ah[4], al[4];

        // MLP1 layer1: x (direct regs) -> h image
#pragma unroll
        for (int i = 0; i < 8; i++) { acc[i][0]=acc[i][1]=acc[i][2]=acc[i][3]=0.f; }
#pragma unroll
        for (int kc = 0; kc < 4; kc++) {
            load_a_direct(x + base, r0, kc, lane, ah, al);
            mma_k16(sb + MLP_W + 0 * 16384, sb + MLP_W + 0 * 16384 + 8192, kc, lane, ah, al, acc);
        }
        epi_to_img(acc, sbias + 0, smp, MLP_HH, MLP_HL, r0, lane);
        __syncwarp();
        // MLP1 layer2: h image -> g_m1
#pragma unroll
        for (int i = 0; i < 8; i++) { acc[i][0]=acc[i][1]=acc[i][2]=acc[i][3]=0.f; }
        warp_mma_k64_img(sb + MLP_HH, sb + MLP_HL,
                         sb + MLP_W + 1 * 16384, sb + MLP_W + 1 * 16384 + 8192, r0, lane, acc);
        epi_to_global_relu(acc, sbias + 64, g_m1 + base, r0, lane);
        __syncwarp();
        // MLP2 layer1: x -> h image (overwrite)
#pragma unroll
        for (int i = 0; i < 8; i++) { acc[i][0]=acc[i][1]=acc[i][2]=acc[i][3]=0.f; }
#pragma unroll
        for (int kc = 0; kc < 4; kc++) {
            load_a_direct(x + base, r0, kc, lane, ah, al);
            mma_k16(sb + MLP_W + 2 * 16384, sb + MLP_W + 2 * 16384 + 8192, kc, lane, ah, al, acc);
        }
        epi_to_img(acc, sbias + 128, smp, MLP_HH, MLP_HL, r0, lane);
        __syncwarp();
        // MLP2 layer2: h image -> g_m2
#pragma unroll
        for (int i = 0; i < 8; i++) { acc[i][0]=acc[i][1]=acc[i][2]=acc[i][3]=0.f; }
        warp_mma_k64_img(sb + MLP_HH, sb + MLP_HL,
                         sb + MLP_W + 3 * 16384, sb + MLP_W + 3 * 16384 + 8192, r0, lane, acc);
        epi_to_global_relu(acc, sbias + 192, g_m2 + base, r0, lane);
        __syncwarp();
    }
}

// ==================== K2: corr + sqrt(relu), cp.async, chunk=4k double-buffered ====================
// smem: m1b 2 x 2048 f (16KB) | m2b 2 x 16384 f (128KB) = 147456 B
#define CORR_SMEM 147456

__global__ void __launch_bounds__(512, 1) corr_kernel()
{
    extern __shared__ float sm[];
    float* m1b = sm;          // buf stride 2048 floats: [8ii][4kk][64c]
    float* m2b = sm + 4096;   // buf stride 16384 floats: [4kk][64j][64c]
    const int t  = threadIdx.x;
    const int b  = blockIdx.x >> 3;
    const int i0 = (blockIdx.x & 7) * 8;
    const int cp = t & 31;
    const int jg = t >> 5;
    const float* M1 = g_m1 + (size_t)b * 262144 + (size_t)i0 * 4096;
    const float* M2 = g_m2 + (size_t)b * 262144;

    u64 acc[8][4];
#pragma unroll
    for (int ii = 0; ii < 8; ii++)
#pragma unroll
        for (int jj = 0; jj < 4; jj++) acc[ii][jj] = 0ull;

    // stage chunk ch (k = 4*ch .. 4*ch+3) into buffer ch&1
    auto stage = [&](int ch) {
        const int k0 = ch * 4;
        const int buf = ch & 1;
        const float* m2src = M2 + (size_t)k0 * 4096;
        float* m2dst = m2b + buf * 16384;
        for (int i = t; i < 4096; i += 512)
            cp16(m2dst + i * 4, m2src + i * 4);
        {
            int ii = t >> 6;
            int kk = (t >> 4) & 3;
            int c4 = t & 15;
            cp16(m1b + buf * 2048 + ii * 256 + kk * 64 + c4 * 4,
                 M1 + (size_t)ii * 4096 + (size_t)(k0 + kk) * 64 + c4 * 4);
        }
        asm volatile("cp.async.commit_group;" ::: "memory");
    };

    stage(0);
    for (int ch = 0; ch < 16; ch++) {
        if (ch < 15) {
            stage(ch + 1);
            asm volatile("cp.async.wait_group 1;" ::: "memory");
        } else {
            asm volatile("cp.async.wait_group 0;" ::: "memory");
        }
        __syncthreads();
        const int buf = ch & 1;
#pragma unroll
        for (int kk = 0; kk < 4; kk++) {
            u64 a1[8];
#pragma unroll
            for (int ii = 0; ii < 8; ii++)
                a1[ii] = *(const u64*)(m1b + buf * 2048 + ii * 256 + kk * 64 + 2 * cp);
#pragma unroll
            for (int jj = 0; jj < 4; jj++) {
                u64 v = *(const u64*)(m2b + buf * 16384 + kk * 4096 + (jg * 4 + jj) * 64 + 2 * cp);
#pragma unroll
                for (int ii = 0; ii < 8; ii++) acc[ii][jj] = ffma2(acc[ii][jj], a1[ii], v);
            }
        }
        __syncthreads();
    }

    float* H = g_h + (size_t)b * 262144 + (size_t)i0 * 4096;
#pragma unroll
    for (int ii = 0; ii < 8; ii++)
#pragma unroll
        for (int jj = 0; jj < 4; jj++) {
            float2 p = u2f(acc[ii][jj]);
            float2 o;
            o.x = sqrtf(fmaxf(p.x, 0.f));
            o.y = sqrtf(fmaxf(p.y, 0.f));
            *(float2*)(H + (size_t)(ii * 64 + jg * 4 + jj) * 64 + 2 * cp) = o;
        }
}

// ==================== K3: z1 = [x,h] @ uW1 + ub1, persistent + stats ====================
#define G1_W    0u          /* m4 at 0, m5 at 16384 */
#define G1_REDS 32768u
#define G1_REDQ 34816u
#define G1_BIAS 36864u
#define G1_SMEM 37120

__global__ void __launch_bounds__(256, 2) gemm1_mma_kernel(const float* __restrict__ x,
                                                           const float* __restrict__ ub1)
{
    extern __shared__ __align__(16) char smp[];
    const uint32_t sb = smem_u32(smp);
    const int t = threadIdx.x;
    const int w = t >> 5, lane = t & 31;
    const int r0 = w * 16;
    float* red_s = (float*)(smp + G1_REDS);
    float* red_q = (float*)(smp + G1_REDQ);
    float* sbias = (float*)(smp + G1_BIAS);

    {
        const uint4* src = (const uint4*)(g_wimg + 4 * 16384);
        uint4* dst = (uint4*)smp;
        for (int i = t; i < 2048; i += 256) dst[i] = src[i];
    }
    if (t < 64) sbias[t] = ub1[t];
    __syncthreads();

    float s_run = 0.f, q_run = 0.f;

    for (int tile = blockIdx.x; tile < NTILES; tile += gridDim.x) {
        const size_t base = (size_t)tile * 8192;
        float acc[8][4];
        uint32_t ah[4], al[4];
#pragma unroll
        for (int i = 0; i < 8; i++) { acc[i][0]=acc[i][1]=acc[i][2]=acc[i][3]=0.f; }
#pragma unroll
        for (int kc = 0; kc < 4; kc++) {
            load_a_direct(x + base, r0, kc, lane, ah, al);
            mma_k16(sb + G1_W, sb + G1_W + 8192, kc, lane, ah, al, acc);
        }
#pragma unroll
        for (int kc = 0; kc < 4; kc++) {
            load_a_direct(g_h + base, r0, kc, lane, ah, al);
            mma_k16(sb + G1_W + 16384, sb + G1_W + 16384 + 8192, kc, lane, ah, al, acc);
        }
        epi_stats(acc, sbias, g_m1 + base, r0, lane, red_s, red_q, w);
        __syncthreads();
        if (t < 64) {
            float s = 0.f, q = 0.f;
#pragma unroll
            for (int ww = 0; ww < 8; ww++) { s += red_s[ww * 64 + t]; q += red_q[ww * 64 + t]; }
            s_run += s; q_run += q;
        }
        __syncthreads();
    }
    if (t < 64) {
        g_part[(size_t)blockIdx.x * 128 + t]      = s_run;
        g_part[(size_t)blockIdx.x * 128 + 64 + t] = q_run;
    }
}

// ==================== finalize: parallel (64 CTAs, 1 channel each) ====================
__global__ void __launch_bounds__(256) finalize_kernel(const float* __restrict__ g,
                                                       const float* __restrict__ be,
                                                       float* __restrict__ ss, int count)
{
    __shared__ double reds[256], redq[256];
    const int c = blockIdx.x;          // channel 0..63
    const int t = threadIdx.x;
    double s = 0.0, q = 0.0;
    for (int i = t; i < count; i += 256) {
        s += (double)g_part[(size_t)i * 128 + c];
        q += (double)g_part[(size_t)i * 128 + 64 + c];
    }
    reds[t] = s; redq[t] = q;
    __syncthreads();
#pragma unroll
    for (int step = 128; step > 0; step >>= 1) {
        if (t < step) { reds[t] += reds[t + step]; redq[t] += redq[t + step]; }
        __syncthreads();
    }
    if (t == 0) {
        double mu  = reds[0] / (double)NROWS;
        double var = redq[0] / (double)NROWS - mu * mu;
        float sc = g[c] * rsqrtf((float)var + 1e-5f);
        ss[c]      = sc;
        ss[64 + c] = be[c] - (float)mu * sc;
    }
}

// ==================== K5: z2 = BN1relu(z1) @ uW2 + ub2, persistent + stats ====================
#define G2_W    0u
#define G2_REDS 16384u
#define G2_REDQ 18432u
#define G2_BIAS 20480u
#define G2_SS   20736u
#define G2_SMEM 21248

__global__ void __launch_bounds__(256, 2) gemm2_mma_kernel(const float* __restrict__ ub2)
{
    extern __shared__ __align__(16) char smp[];
    const uint32_t sb = smem_u32(smp);
    const int t = threadIdx.x;
    const int w = t >> 5, lane = t & 31;
    const int r0 = w * 16;
    float* red_s = (float*)(smp + G2_REDS);
    float* red_q = (float*)(smp + G2_REDQ);
    float* sbias = (float*)(smp + G2_BIAS);
    float* ss    = (float*)(smp + G2_SS);

    {
        const uint4* src = (const uint4*)(g_wimg + 6 * 16384);
        uint4* dst = (uint4*)smp;
        for (int i = t; i < 1024; i += 256) dst[i] = src[i];
    }
    if (t < 64) sbias[t] = ub2[t];
    if (t < 128) ss[t] = g_ss1[t];
    __syncthreads();

    float s_run = 0.f, q_run = 0.f;

    for (int tile = blockIdx.x; tile < NTILES; tile += gridDim.x) {
        const size_t base = (size_t)tile * 8192;
        float acc[8][4];
        uint32_t ah[4], al[4];
#pragma unroll
        for (int i = 0; i < 8; i++) { acc[i][0]=acc[i][1]=acc[i][2]=acc[i][3]=0.f; }
#pragma unroll
        for (int kc = 0; kc < 4; kc++) {
            load_a_bn(g_m1 + base, ss, r0, kc, lane, ah, al);
            mma_k16(sb + G2_W, sb + G2_W + 8192, kc, lane, ah, al, acc);
        }
        epi_stats(acc, sbias, g_m2 + base, r0, lane, red_s, red_q, w);
        __syncthreads();
        if (t < 64) {
            float s = 0.f, q = 0.f;
#pragma unroll
            for (int ww = 0; ww < 8; ww++) { s += red_s[ww * 64 + t]; q += red_q[ww * 64 + t]; }
            s_run += s; q_run += q;
        }
        __syncthreads();
    }
    if (t < 64) {
        g_part[(size_t)blockIdx.x * 128 + t]      = s_run;
        g_part[(size_t)blockIdx.x * 128 + 64 + t] = q_run;
    }
}

// ==================== K7: out = BN2relu(z2) + x ====================
__global__ void __launch_bounds__(256) final_kernel(const float* __restrict__ x,
                                                    float* __restrict__ out)
{
    __shared__ float ss[128];
    if (threadIdx.x < 128) ss[threadIdx.x] = g_ss2[threadIdx.x];
    __syncthreads();
    const size_t total4 = NROWS * 64 / 4;
    for (size_t v = (size_t)blockIdx.x * 256 + threadIdx.x; v < total4;
         v += (size_t)gridDim.x * 256) {
        int c0 = ((int)(v & 15)) * 4;
        float4 z = *(const float4*)((const float*)g_m2 + v * 4);
        float4 xv = *(const float4*)(x + v * 4);
        float4 o;
        o.x = fmaxf(z.x * ss[c0 + 0] + ss[64 + c0 + 0], 0.f) + xv.x;
        o.y = fmaxf(z.y * ss[c0 + 1] + ss[64 + c0 + 1], 0.f) + xv.y;
        o.z = fmaxf(z.z * ss[c0 + 2] + ss[64 + c0 + 2], 0.f) + xv.z;
        o.w = fmaxf(z.w * ss[c0 + 3] + ss[64 + c0 + 3], 0.f) + xv.w;
        *(float4*)(out + v * 4) = o;
    }
}

// ==================== host ====================
extern "C" void kernel_launch(void* const* d_in, const int* in_sizes, int n_in,
                              void* d_out, int out_size)
{
    const float* x    = (const float*)d_in[0];
    const float* w11  = (const float*)d_in[1];
    const float* b11  = (const float*)d_in[2];
    const float* w12  = (const float*)d_in[3];
    const float* b12  = (const float*)d_in[4];
    const float* w21  = (const float*)d_in[5];
    const float* b21  = (const float*)d_in[6];
    const float* w22  = (const float*)d_in[7];
    const float* b22  = (const float*)d_in[8];
    const float* uW1  = (const float*)d_in[9];
    const float* ub1  = (const float*)d_in[10];
    const float* g1   = (const float*)d_in[11];
    const float* be1  = (const float*)d_in[12];
    const float* uW2  = (const float*)d_in[13];
    const float* ub2  = (const float*)d_in[14];
    const float* g2   = (const float*)d_in[15];
    const float* be2  = (const float*)d_in[16];
    float* out = (float*)d_out;

    float *ss1, *ss2;
    cudaGetSymbolAddress((void**)&ss1, g_ss1);
    cudaGetSymbolAddress((void**)&ss2, g_ss2);

    cudaFuncSetAttribute(mlp_mma_kernel,   cudaFuncAttributeMaxDynamicSharedMemorySize, MLP_SMEM);
    cudaFuncSetAttribute(corr_kernel,      cudaFuncAttributeMaxDynamicSharedMemorySize, CORR_SMEM);
    cudaFuncSetAttribute(gemm1_mma_kernel, cudaFuncAttributeMaxDynamicSharedMemorySize, G1_SMEM);
    cudaFuncSetAttribute(gemm2_mma_kernel, cudaFuncAttributeMaxDynamicSharedMemorySize, G2_SMEM);

    prep_kernel<<<112, 256>>>(w11, w12, w21, w22, uW1, uW2);
    mlp_mma_kernel<<<NG, 256, MLP_SMEM>>>(x, b11, b12, b21, b22);
    corr_kernel<<<2048, 512, CORR_SMEM>>>();
    gemm1_mma_kernel<<<NG, 256, G1_SMEM>>>(x, ub1);
    finalize_kernel<<<64, 256>>>(g1, be1, ss1, NG);
    gemm2_mma_kernel<<<NG, 256, G2_SMEM>>>(ub2);
    finalize_kernel<<<64, 256>>>(g2, be2, ss2, NG);
    final_kernel<<<16384, 256>>>(x, out);
}

// round 17
// speedup vs baseline: 1.0160x; 1.0042x over previous
#include <cuda_runtime.h>
#include <cuda_bf16.h>
#include <math.h>
#include <stdint.h>

typedef unsigned long long u64;
#define NROWS 1048576ull
#define NTILES 8192
#define NG 296            /* persistent grid: 2 CTAs x 148 SMs */

// ==================== device globals (no runtime alloc) ====================
__device__ float g_m1[NROWS * 64];      // m1, reused as z1
__device__ float g_m2[NROWS * 64];      // m2, reused as z2
__device__ float g_h [NROWS * 64];      // sqrt(relu(corr))
__device__ float g_part[NG * 128];      // per-CTA [sum(64)|sumsq(64)]
__device__ float g_ss1[128];            // BN1 [scale|shift]
__device__ float g_ss2[128];            // BN2
// 7 weight matrices as pre-swizzled SW128 images: [m][hi 8KB][lo 8KB]
// m: 0=w11 1=w12 2=w21 3=w22 ([n][k])  4=uW1^T k<64  5=uW1^T k>=64  6=uW2^T
__device__ __align__(16) unsigned char g_wimg[7 * 16384];

// ==================== helpers ====================
__device__ __forceinline__ uint32_t smem_u32(const void* p) {
    uint32_t a;
    asm("{ .reg .u64 t; cvta.to.shared.u64 t, %1; cvt.u32.u64 %0, t; }" : "=r"(a) : "l"(p));
    return a;
}
__device__ __forceinline__ uint32_t sw128(uint32_t b) { return b ^ ((b >> 3) & 0x70); }

__device__ __forceinline__ u64 ffma2(u64 acc, u64 a, u64 b) {
    u64 d;
    asm("fma.rn.f32x2 %0, %1, %2, %3;" : "=l"(d) : "l"(a), "l"(b), "l"(acc));
    return d;
}
__device__ __forceinline__ float2 u2f(u64 v) {
    float2 f;
    asm("mov.b64 {%0, %1}, %2;" : "=f"(f.x), "=f"(f.y) : "l"(v));
    return f;
}

__device__ __forceinline__ void split2(float2 v, uint32_t& hi, uint32_t& lo) {
    __nv_bfloat162 h2 = __float22bfloat162_rn(v);
    float2 hf = __bfloat1622float2(h2);
    __nv_bfloat162 l2 = __float22bfloat162_rn(make_float2(v.x - hf.x, v.y - hf.y));
    hi = *(uint32_t*)&h2;
    lo = *(uint32_t*)&l2;
}

__device__ __forceinline__ void cp16(float* dst_smem, const void* src) {
    uint32_t d = smem_u32(dst_smem);
    asm volatile("cp.async.cg.shared.global [%0], [%1], 16;" :: "r"(d), "l"(src));
}

// ==================== HMMA building blocks ====================
__device__ __forceinline__ void ldsm4(uint32_t addr, uint32_t r[4]) {
    asm volatile("ldmatrix.sync.aligned.m8n8.x4.shared.b16 {%0,%1,%2,%3}, [%4];"
        : "=r"(r[0]), "=r"(r[1]), "=r"(r[2]), "=r"(r[3]) : "r"(addr));
}
__device__ __forceinline__ void mma16816(float (&d)[4], const uint32_t (&a)[4],
                                         uint32_t b0, uint32_t b1) {
    asm volatile("mma.sync.aligned.m16n8k16.row.col.f32.bf16.bf16.f32 "
        "{%0,%1,%2,%3}, {%4,%5,%6,%7}, {%8,%9}, {%0,%1,%2,%3};"
        : "+f"(d[0]), "+f"(d[1]), "+f"(d[2]), "+f"(d[3])
        : "r"(a[0]), "r"(a[1]), "r"(a[2]), "r"(a[3]), "r"(b0), "r"(b1));
}

// Direct-register A fragment from a row-major [128][64] fp32 tile, split hi/lo.
__device__ __forceinline__ void load_a_direct(const float* __restrict__ tile, int r0,
                                              int kc, int lane,
                                              uint32_t ah[4], uint32_t al[4]) {
    const float* p = tile + (size_t)(r0 + (lane >> 2)) * 64 + kc * 16 + (lane & 3) * 2;
    float2 v00 = *(const float2*)p;
    float2 v01 = *(const float2*)(p + 8);
    float2 v10 = *(const float2*)(p + 512);
    float2 v11 = *(const float2*)(p + 520);
    split2(v00, ah[0], al[0]); split2(v10, ah[1], al[1]);
    split2(v01, ah[2], al[2]); split2(v11, ah[3], al[3]);
}

// A fragment from a padded smem tile (row stride 72 floats), split hi/lo.
// Stride 72: LDS.64 quads hit bank offsets {0,8,16,24} per 16-lane phase -> conflict-free.
__device__ __forceinline__ void load_a_smem(const float* __restrict__ sA, int r0,
                                            int kc, int lane,
                                            uint32_t ah[4], uint32_t al[4]) {
    const float* p = sA + (r0 + (lane >> 2)) * 72 + kc * 16 + (lane & 3) * 2;
    float2 v00 = *(const float2*)p;
    float2 v01 = *(const float2*)(p + 8);
    float2 v10 = *(const float2*)(p + 576);
    float2 v11 = *(const float2*)(p + 584);
    split2(v00, ah[0], al[0]); split2(v10, ah[1], al[1]);
    split2(v01, ah[2], al[2]); split2(v11, ah[3], al[3]);
}

// Same but applies BN1-relu (scale/shift in smem ss[0..63], [64..127]).
__device__ __forceinline__ void load_a_bn(const float* __restrict__ tile,
                                          const float* __restrict__ sss, int r0,
                                          int kc, int lane,
                                          uint32_t ah[4], uint32_t al[4]) {
    const int c = kc * 16 + (lane & 3) * 2;
    float2 s0 = *(const float2*)(sss + c),      s8 = *(const float2*)(sss + c + 8);
    float2 h0 = *(const float2*)(sss + 64 + c), h8 = *(const float2*)(sss + 64 + c + 8);
    const float* p = tile + (size_t)(r0 + (lane >> 2)) * 64 + c;
    float2 v00 = *(const float2*)p;
    float2 v01 = *(const float2*)(p + 8);
    float2 v10 = *(const float2*)(p + 512);
    float2 v11 = *(const float2*)(p + 520);
    v00.x = fmaxf(v00.x * s0.x + h0.x, 0.f); v00.y = fmaxf(v00.y * s0.y + h0.y, 0.f);
    v10.x = fmaxf(v10.x * s0.x + h0.x, 0.f); v10.y = fmaxf(v10.y * s0.y + h0.y, 0.f);
    v01.x = fmaxf(v01.x * s8.x + h8.x, 0.f); v01.y = fmaxf(v01.y * s8.y + h8.y, 0.f);
    v11.x = fmaxf(v11.x * s8.x + h8.x, 0.f); v11.y = fmaxf(v11.y * s8.y + h8.y, 0.f);
    split2(v00, ah[0], al[0]); split2(v10, ah[1], al[1]);
    split2(v01, ah[2], al[2]); split2(v11, ah[3], al[3]);
}

// One k16 step vs B images (full n=64): Ah*Bh + Al*Bh + Ah*Bl.
__device__ __forceinline__ void mma_k16(uint32_t bH, uint32_t bL, int kc, int lane,
                                        const uint32_t (&ah)[4], const uint32_t (&al)[4],
                                        float (&acc)[8][4]) {
    const int grp = lane >> 3, li = lane & 7;
    const int brow_off = li + ((grp >> 1) << 3);
    const uint32_t cb = (uint32_t)((kc * 16 + ((grp & 1) << 3)) * 2);
#pragma unroll
    for (int n2 = 0; n2 < 4; n2++) {
        int brow = n2 * 16 + brow_off;
        uint32_t bx = (uint32_t)(brow * 128) + (cb ^ (uint32_t)((brow & 7) << 4));
        uint32_t b[4];
        ldsm4(bH + bx, b);
        mma16816(acc[n2 * 2],     ah, b[0], b[1]);
        mma16816(acc[n2 * 2 + 1], ah, b[2], b[3]);
        mma16816(acc[n2 * 2],     al, b[0], b[1]);
        mma16816(acc[n2 * 2 + 1], al, b[2], b[3]);
        ldsm4(bL + bx, b);
        mma16816(acc[n2 * 2],     ah, b[0], b[1]);
        mma16816(acc[n2 * 2 + 1], ah, b[2], b[3]);
    }
}

// Full K=64 matmul with A from an SW128 smem image.
__device__ __forceinline__ void warp_mma_k64_img(uint32_t aH, uint32_t aL,
                                                 uint32_t bH, uint32_t bL,
                                                 int r0, int lane, float (&acc)[8][4])
{
    const int grp = lane >> 3, li = lane & 7;
    const int arow = r0 + li + ((grp & 1) << 3);
    const uint32_t arbase = (uint32_t)(arow * 128);
    const uint32_t arxor = (uint32_t)((arow & 7) << 4);
    const int akhi = (grp >> 1) << 3;
#pragma unroll
    for (int kk = 0; kk < 4; kk++) {
        uint32_t acb = (uint32_t)((kk * 16 + akhi) * 2);
        uint32_t ah[4], al[4];
        ldsm4(aH + arbase + (acb ^ arxor), ah);
        ldsm4(aL + arbase + (acb ^ arxor), al);
        mma_k16(bH, bL, kk, lane, ah, al, acc);
    }
}

// epilogue: relu(acc+bias) -> split-store into smem image (warp-private rows)
__device__ __forceinline__ void epi_to_img(float (&acc)[8][4], const float* bias,
                                           char* smp, uint32_t hiOff, uint32_t loOff,
                                           int r0, int lane)
{
    const int tr = lane >> 2, tc2 = lane & 3;
    const int r1 = r0 + tr, r2 = r1 + 8;
    const uint32_t x1 = (uint32_t)((r1 & 7) << 4), x2 = (uint32_t)((r2 & 7) << 4);
#pragma unroll
    for (int nt = 0; nt < 8; nt++) {
        int c0 = nt * 8 + 2 * tc2;
        float b0 = bias[c0], b1 = bias[c0 + 1];
        uint32_t cb = (uint32_t)(c0 * 2);
        uint32_t hi, lo;
        float2 v;
        v.x = fmaxf(acc[nt][0] + b0, 0.f);
        v.y = fmaxf(acc[nt][1] + b1, 0.f);
        split2(v, hi, lo);
        *(uint32_t*)(smp + hiOff + r1 * 128 + (cb ^ x1)) = hi;
        *(uint32_t*)(smp + loOff + r1 * 128 + (cb ^ x1)) = lo;
        v.x = fmaxf(acc[nt][2] + b0, 0.f);
        v.y = fmaxf(acc[nt][3] + b1, 0.f);
        split2(v, hi, lo);
        *(uint32_t*)(smp + hiOff + r2 * 128 + (cb ^ x2)) = hi;
        *(uint32_t*)(smp + loOff + r2 * 128 + (cb ^ x2)) = lo;
    }
}

// epilogue: relu(acc+bias) -> fp32 global rows
__device__ __forceinline__ void epi_to_global_relu(float (&acc)[8][4], const float* bias,
                                                   float* gdst, int r0, int lane)
{
    const int tr = lane >> 2, tc2 = lane & 3;
    const int r1 = r0 + tr, r2 = r1 + 8;
#pragma unroll
    for (int nt = 0; nt < 8; nt++) {
        int c0 = nt * 8 + 2 * tc2;
        float b0 = bias[c0], b1 = bias[c0 + 1];
        *(float2*)(gdst + (size_t)r1 * 64 + c0) =
            make_float2(fmaxf(acc[nt][0] + b0, 0.f), fmaxf(acc[nt][1] + b1, 0.f));
        *(float2*)(gdst + (size_t)r2 * 64 + c0) =
            make_float2(fmaxf(acc[nt][2] + b0, 0.f), fmaxf(acc[nt][3] + b1, 0.f));
    }
}

// epilogue: z=acc+bias -> global + warp shuffle-reduced sum/sumsq into red buffers
__device__ __forceinline__ void epi_stats(float (&acc)[8][4], const float* bias,
                                          float* gdst, int r0, int lane,
                                          float* red_s, float* red_q, int w)
{
    const int tr = lane >> 2, tc2 = lane & 3;
    const int r1 = r0 + tr, r2 = r1 + 8;
#pragma unroll
    for (int nt = 0; nt < 8; nt++) {
        int c0 = nt * 8 + 2 * tc2;
        float b0 = bias[c0], b1 = bias[c0 + 1];
        float z00 = acc[nt][0] + b0, z01 = acc[nt][1] + b1;
        float z10 = acc[nt][2] + b0, z11 = acc[nt][3] + b1;
        *(float2*)(gdst + (size_t)r1 * 64 + c0) = make_float2(z00, z01);
        *(float2*)(gdst + (size_t)r2 * 64 + c0) = make_float2(z10, z11);
        float s0 = z00 + z10, s1 = z01 + z11;
        float q0 = z00 * z00 + z10 * z10, q1 = z01 * z01 + z11 * z11;
#pragma unroll
        for (int m = 4; m < 32; m <<= 1) {
            s0 += __shfl_xor_sync(0xffffffffu, s0, m);
            s1 += __shfl_xor_sync(0xffffffffu, s1, m);
            q0 += __shfl_xor_sync(0xffffffffu, q0, m);
            q1 += __shfl_xor_sync(0xffffffffu, q1, m);
        }
        if (tr == 0) {
            red_s[w * 64 + c0]     = s0;
            red_s[w * 64 + c0 + 1] = s1;
            red_q[w * 64 + c0]     = q0;
            red_q[w * 64 + c0 + 1] = q1;
        }
    }
}

// ==================== prep: weights -> bf16 hi/lo SW128 images (parallel) ====================
__global__ void prep_kernel(const float* __restrict__ w11, const float* __restrict__ w12,
                            const float* __restrict__ w21, const float* __restrict__ w22,
                            const float* __restrict__ uW1, const float* __restrict__ uW2)
{
    int idx = blockIdx.x * 256 + threadIdx.x;
    if (idx >= 7 * 4096) return;
    int m = idx >> 12, e = idx & 4095, n = e >> 6, k = e & 63;
    float v;
    if      (m == 0) v = w11[e];
    else if (m == 1) v = w12[e];
    else if (m == 2) v = w21[e];
    else if (m == 3) v = w22[e];
    else if (m == 4) v = uW1[k * 64 + n];
    else if (m == 5) v = uW1[(64 + k) * 64 + n];
    else             v = uW2[k * 64 + n];
    __nv_bfloat16 hi = __float2bfloat16(v);
    __nv_bfloat16 lo = __float2bfloat16(v - __bfloat162float(hi));
    uint32_t sw = sw128((uint32_t)(n * 128 + k * 2));
    *(__nv_bfloat16*)(g_wimg + m * 16384 + sw)        = hi;
    *(__nv_bfloat16*)(g_wimg + m * 16384 + 8192 + sw) = lo;
}

// ==================== K1: fused 4-layer MLP pair, persistent multi-tile ====================
#define MLP_HH 0u
#define MLP_HL 16384u
#define MLP_W  32768u       /* 4 x 16KB images */
#define MLP_BIAS 98304u     /* 256 floats */
#define MLP_SMEM 99328

__global__ void __launch_bounds__(256, 2) mlp_mma_kernel(const float* __restrict__ x,
    const float* __restrict__ b11, const float* __restrict__ b12,
    const float* __restrict__ b21, const float* __restrict__ b22)
{
    extern __shared__ __align__(16) char smp[];
    const uint32_t sb = smem_u32(smp);
    const int t = threadIdx.x;
    const int w = t >> 5, lane = t & 31;
    const int r0 = w * 16;

    {
        const uint4* src = (const uint4*)g_wimg;
        uint4* dst = (uint4*)(smp + MLP_W);
        for (int i = t; i < 4096; i += 256) dst[i] = src[i];
    }
    float* sbias = (float*)(smp + MLP_BIAS);
    if (t < 64) {
        sbias[t]       = b11[t];
        sbias[64 + t]  = b12[t];
        sbias[128 + t] = b21[t];
        sbias[192 + t] = b22[t];
    }
    __syncthreads();

    for (int tile = blockIdx.x; tile < NTILES; tile += gridDim.x) {
        const size_t base = (size_t)tile * 8192;
        float acc[8][4];
        uint32_t ah[4], al[4];

        // MLP1 layer1: x (direct regs) -> h image
#pragma unroll
        for (int i = 0; i < 8; i++) { acc[i][0]=acc[i][1]=acc[i][2]=acc[i][3]=0.f; }
#pragma unroll
        for (int kc = 0; kc < 4; kc++) {
            load_a_direct(x + base, r0, kc, lane, ah, al);
            mma_k16(sb + MLP_W + 0 * 16384, sb + MLP_W + 0 * 16384 + 8192, kc, lane, ah, al, acc);
        }
        epi_to_img(acc, sbias + 0, smp, MLP_HH, MLP_HL, r0, lane);
        __syncwarp();
        // MLP1 layer2: h image -> g_m1
#pragma unroll
        for (int i = 0; i < 8; i++) { acc[i][0]=acc[i][1]=acc[i][2]=acc[i][3]=0.f; }
        warp_mma_k64_img(sb + MLP_HH, sb + MLP_HL,
                         sb + MLP_W + 1 * 16384, sb + MLP_W + 1 * 16384 + 8192, r0, lane, acc);
        epi_to_global_relu(acc, sbias + 64, g_m1 + base, r0, lane);
        __syncwarp();
        // MLP2 layer1: x -> h image (overwrite)
#pragma unroll
        for (int i = 0; i < 8; i++) { acc[i][0]=acc[i][1]=acc[i][2]=acc[i][3]=0.f; }
#pragma unroll
        for (int kc = 0; kc < 4; kc++) {
            load_a_direct(x + base, r0, kc, lane, ah, al);
            mma_k16(sb + MLP_W + 2 * 16384, sb + MLP_W + 2 * 16384 + 8192, kc, lane, ah, al, acc);
        }
        epi_to_img(acc, sbias + 128, smp, MLP_HH, MLP_HL, r0, lane);
        __syncwarp();
        // MLP2 layer2: h image -> g_m2
#pragma unroll
        for (int i = 0; i < 8; i++) { acc[i][0]=acc[i][1]=acc[i][2]=acc[i][3]=0.f; }
        warp_mma_k64_img(sb + MLP_HH, sb + MLP_HL,
                         sb + MLP_W + 3 * 16384, sb + MLP_W + 3 * 16384 + 8192, r0, lane, acc);
        epi_to_global_relu(acc, sbias + 192, g_m2 + base, r0, lane);
        __syncwarp();
    }
}

// ==================== K2: corr + sqrt(relu), cp.async, chunk=4k double-buffered ====================
// smem: m1b 2 x 2048 f (16KB) | m2b 2 x 16384 f (128KB) = 147456 B
#define CORR_SMEM 147456

__global__ void __launch_bounds__(512, 1) corr_kernel()
{
    extern __shared__ float sm[];
    float* m1b = sm;          // buf stride 2048 floats: [8ii][4kk][64c]
    float* m2b = sm + 4096;   // buf stride 16384 floats: [4kk][64j][64c]
    const int t  = threadIdx.x;
    const int b  = blockIdx.x >> 3;
    const int i0 = (blockIdx.x & 7) * 8;
    const int cp = t & 31;
    const int jg = t >> 5;
    const float* M1 = g_m1 + (size_t)b * 262144 + (size_t)i0 * 4096;
    const float* M2 = g_m2 + (size_t)b * 262144;

    u64 acc[8][4];
#pragma unroll
    for (int ii = 0; ii < 8; ii++)
#pragma unroll
        for (int jj = 0; jj < 4; jj++) acc[ii][jj] = 0ull;

    // stage chunk ch (k = 4*ch .. 4*ch+3) into buffer ch&1
    auto stage = [&](int ch) {
        const int k0 = ch * 4;
        const int buf = ch & 1;
        const float* m2src = M2 + (size_t)k0 * 4096;
        float* m2dst = m2b + buf * 16384;
        for (int i = t; i < 4096; i += 512)
            cp16(m2dst + i * 4, m2src + i * 4);
        {
            int ii = t >> 6;
            int kk = (t >> 4) & 3;
            int c4 = t & 15;
            cp16(m1b + buf * 2048 + ii * 256 + kk * 64 + c4 * 4,
                 M1 + (size_t)ii * 4096 + (size_t)(k0 + kk) * 64 + c4 * 4);
        }
        asm volatile("cp.async.commit_group;" ::: "memory");
    };

    stage(0);
    for (int ch = 0; ch < 16; ch++) {
        if (ch < 15) {
            stage(ch + 1);
            asm volatile("cp.async.wait_group 1;" ::: "memory");
        } else {
            asm volatile("cp.async.wait_group 0;" ::: "memory");
        }
        __syncthreads();
        const int buf = ch & 1;
#pragma unroll
        for (int kk = 0; kk < 4; kk++) {
            u64 a1[8];
#pragma unroll
            for (int ii = 0; ii < 8; ii++)
                a1[ii] = *(const u64*)(m1b + buf * 2048 + ii * 256 + kk * 64 + 2 * cp);
#pragma unroll
            for (int jj = 0; jj < 4; jj++) {
                u64 v = *(const u64*)(m2b + buf * 16384 + kk * 4096 + (jg * 4 + jj) * 64 + 2 * cp);
#pragma unroll
                for (int ii = 0; ii < 8; ii++) acc[ii][jj] = ffma2(acc[ii][jj], a1[ii], v);
            }
        }
        __syncthreads();
    }

    float* H = g_h + (size_t)b * 262144 + (size_t)i0 * 4096;
#pragma unroll
    for (int ii = 0; ii < 8; ii++)
#pragma unroll
        for (int jj = 0; jj < 4; jj++) {
            float2 p = u2f(acc[ii][jj]);
            float2 o;
            o.x = sqrtf(fmaxf(p.x, 0.f));
            o.y = sqrtf(fmaxf(p.y, 0.f));
            *(float2*)(H + (size_t)(ii * 64 + jg * 4 + jj) * 64 + 2 * cp) = o;
        }
}

// ==================== K3: z1 = [x,h] @ uW1 + ub1, cp.async-staged A ====================
// smem: W 32KB | XS 36864 | HS 36864 | REDS 2KB | REDQ 2KB | BIAS 256B
#define G1_W    0u
#define G1_XS   32768u      /* 128 rows x stride 72 floats */
#define G1_HS   69632u
#define G1_REDS 106496u
#define G1_REDQ 108544u
#define G1_BIAS 110592u
#define G1_SMEM 110848

__global__ void __launch_bounds__(256, 2) gemm1_mma_kernel(const float* __restrict__ x,
                                                           const float* __restrict__ ub1)
{
    extern __shared__ __align__(16) char smp[];
    const uint32_t sb = smem_u32(smp);
    const int t = threadIdx.x;
    const int w = t >> 5, lane = t & 31;
    const int r0 = w * 16;
    float* xs    = (float*)(smp + G1_XS);
    float* hs    = (float*)(smp + G1_HS);
    float* red_s = (float*)(smp + G1_REDS);
    float* red_q = (float*)(smp + G1_REDQ);
    float* sbias = (float*)(smp + G1_BIAS);

    {
        const uint4* src = (const uint4*)(g_wimg + 4 * 16384);
        uint4* dst = (uint4*)smp;
        for (int i = t; i < 2048; i += 256) dst[i] = src[i];
    }
    if (t < 64) sbias[t] = ub1[t];
    __syncthreads();

    float s_run = 0.f, q_run = 0.f;

    for (int tile = blockIdx.x; tile < NTILES; tile += gridDim.x) {
        const size_t base = (size_t)tile * 8192;

        // ---- stage x and h tiles into padded smem (coalesced cp.async) ----
        for (int i = t; i < 2048; i += 256) {
            int row = i >> 4, c4 = i & 15;
            cp16(xs + row * 72 + c4 * 4, x   + base + (size_t)row * 64 + c4 * 4);
            cp16(hs + row * 72 + c4 * 4, g_h + base + (size_t)row * 64 + c4 * 4);
        }
        asm volatile("cp.async.commit_group;" ::: "memory");
        asm volatile("cp.async.wait_group 0;" ::: "memory");
        __syncthreads();

        float acc[8][4];
        uint32_t ah[4], al[4];
#pragma unroll
        for (int i = 0; i < 8; i++) { acc[i][0]=acc[i][1]=acc[i][2]=acc[i][3]=0.f; }
#pragma unroll
        for (int kc = 0; kc < 4; kc++) {
            load_a_smem(xs, r0, kc, lane, ah, al);
            mma_k16(sb + G1_W, sb + G1_W + 8192, kc, lane, ah, al, acc);
        }
#pragma unroll
        for (int kc = 0; kc < 4; kc++) {
            load_a_smem(hs, r0, kc, lane, ah, al);
            mma_k16(sb + G1_W + 16384, sb + G1_W + 16384 + 8192, kc, lane, ah, al, acc);
        }
        epi_stats(acc, sbias, g_m1 + base, r0, lane, red_s, red_q, w);
        __syncthreads();
        if (t < 64) {
            float s = 0.f, q = 0.f;
#pragma unroll
            for (int ww = 0; ww < 8; ww++) { s += red_s[ww * 64 + t]; q += red_q[ww * 64 + t]; }
            s_run += s; q_run += q;
        }
        __syncthreads();
    }
    if (t < 64) {
        g_part[(size_t)blockIdx.x * 128 + t]      = s_run;
        g_part[(size_t)blockIdx.x * 128 + 64 + t] = q_run;
    }
}

// ==================== finalize: parallel (64 CTAs, 1 channel each) ====================
__global__ void __launch_bounds__(256) finalize_kernel(const float* __restrict__ g,
                                                       const float* __restrict__ be,
                                                       float* __restrict__ ss, int count)
{
    __shared__ double reds[256], redq[256];
    const int c = blockIdx.x;          // channel 0..63
    const int t = threadIdx.x;
    double s = 0.0, q = 0.0;
    for (int i = t; i < count; i += 256) {
        s += (double)g_part[(size_t)i * 128 + c];
        q += (double)g_part[(size_t)i * 128 + 64 + c];
    }
    reds[t] = s; redq[t] = q;
    __syncthreads();
#pragma unroll
    for (int step = 128; step > 0; step >>= 1) {
        if (t < step) { reds[t] += reds[t + step]; redq[t] += redq[t + step]; }
        __syncthreads();
    }
    if (t == 0) {
        double mu  = reds[0] / (double)NROWS;
        double var = redq[0] / (double)NROWS - mu * mu;
        float sc = g[c] * rsqrtf((float)var + 1e-5f);
        ss[c]      = sc;
        ss[64 + c] = be[c] - (float)mu * sc;
    }
}

// ==================== K5: z2 = BN1relu(z1) @ uW2 + ub2, persistent + stats ====================
#define G2_W    0u
#define G2_REDS 16384u
#define G2_REDQ 18432u
#define G2_BIAS 20480u
#define G2_SS   20736u
#define G2_SMEM 21248

__global__ void __launch_bounds__(256, 2) gemm2_mma_kernel(const float* __restrict__ ub2)
{
    extern __shared__ __align__(16) char smp[];
    const uint32_t sb = smem_u32(smp);
    const int t = threadIdx.x;
    const int w = t >> 5, lane = t & 31;
    const int r0 = w * 16;
    float* red_s = (float*)(smp + G2_REDS);
    float* red_q = (float*)(smp + G2_REDQ);
    float* sbias = (float*)(smp + G2_BIAS);
    float* ss    = (float*)(smp + G2_SS);

    {
        const uint4* src = (const uint4*)(g_wimg + 6 * 16384);
        uint4* dst = (uint4*)smp;
        for (int i = t; i < 1024; i += 256) dst[i] = src[i];
    }
    if (t < 64) sbias[t] = ub2[t];
    if (t < 128) ss[t] = g_ss1[t];
    __syncthreads();

    float s_run = 0.f, q_run = 0.f;

    for (int tile = blockIdx.x; tile < NTILES; tile += gridDim.x) {
        const size_t base = (size_t)tile * 8192;
        float acc[8][4];
        uint32_t ah[4], al[4];
#pragma unroll
        for (int i = 0; i < 8; i++) { acc[i][0]=acc[i][1]=acc[i][2]=acc[i][3]=0.f; }
#pragma unroll
        for (int kc = 0; kc < 4; kc++) {
            load_a_bn(g_m1 + base, ss, r0, kc, lane, ah, al);
            mma_k16(sb + G2_W, sb + G2_W + 8192, kc, lane, ah, al, acc);
        }
        epi_stats(acc, sbias, g_m2 + base, r0, lane, red_s, red_q, w);
        __syncthreads();
        if (t < 64) {
            float s = 0.f, q = 0.f;
#pragma unroll
            for (int ww = 0; ww < 8; ww++) { s += red_s[ww * 64 + t]; q += red_q[ww * 64 + t]; }
            s_run += s; q_run += q;
        }
        __syncthreads();
    }
    if (t < 64) {
        g_part[(size_t)blockIdx.x * 128 + t]      = s_run;
        g_part[(size_t)blockIdx.x * 128 + 64 + t] = q_run;
    }
}

// ==================== K7: out = BN2relu(z2) + x ====================
__global__ void __launch_bounds__(256) final_kernel(const float* __restrict__ x,
                                                    float* __restrict__ out)
{
    __shared__ float ss[128];
    if (threadIdx.x < 128) ss[threadIdx.x] = g_ss2[threadIdx.x];
    __syncthreads();
    const size_t total4 = NROWS * 64 / 4;
    for (size_t v = (size_t)blockIdx.x * 256 + threadIdx.x; v < total4;
         v += (size_t)gridDim.x * 256) {
        int c0 = ((int)(v & 15)) * 4;
        float4 z = *(const float4*)((const float*)g_m2 + v * 4);
        float4 xv = *(const float4*)(x + v * 4);
        float4 o;
        o.x = fmaxf(z.x * ss[c0 + 0] + ss[64 + c0 + 0], 0.f) + xv.x;
        o.y = fmaxf(z.y * ss[c0 + 1] + ss[64 + c0 + 1], 0.f) + xv.y;
        o.z = fmaxf(z.z * ss[c0 + 2] + ss[64 + c0 + 2], 0.f) + xv.z;
        o.w = fmaxf(z.w * ss[c0 + 3] + ss[64 + c0 + 3], 0.f) + xv.w;
        *(float4*)(out + v * 4) = o;
    }
}

// ==================== host ====================
extern "C" void kernel_launch(void* const* d_in, const int* in_sizes, int n_in,
                              void* d_out, int out_size)
{
    const float* x    = (const float*)d_in[0];
    const float* w11  = (const float*)d_in[1];
    const float* b11  = (const float*)d_in[2];
    const float* w12  = (const float*)d_in[3];
    const float* b12  = (const float*)d_in[4];
    const float* w21  = (const float*)d_in[5];
    const float* b21  = (const float*)d_in[6];
    const float* w22  = (const float*)d_in[7];
    const float* b22  = (const float*)d_in[8];
    const float* uW1  = (const float*)d_in[9];
    const float* ub1  = (const float*)d_in[10];
    const float* g1   = (const float*)d_in[11];
    const float* be1  = (const float*)d_in[12];
    const float* uW2  = (const float*)d_in[13];
    const float* ub2  = (const float*)d_in[14];
    const float* g2   = (const float*)d_in[15];
    const float* be2  = (const float*)d_in[16];
    float* out = (float*)d_out;

    float *ss1, *ss2;
    cudaGetSymbolAddress((void**)&ss1, g_ss1);
    cudaGetSymbolAddress((void**)&ss2, g_ss2);

    cudaFuncSetAttribute(mlp_mma_kernel,   cudaFuncAttributeMaxDynamicSharedMemorySize, MLP_SMEM);
    cudaFuncSetAttribute(corr_kernel,      cudaFuncAttributeMaxDynamicSharedMemorySize, CORR_SMEM);
    cudaFuncSetAttribute(gemm1_mma_kernel, cudaFuncAttributeMaxDynamicSharedMemorySize, G1_SMEM);
    cudaFuncSetAttribute(gemm2_mma_kernel, cudaFuncAttributeMaxDynamicSharedMemorySize, G2_SMEM);

    prep_kernel<<<112, 256>>>(w11, w12, w21, w22, uW1, uW2);
    mlp_mma_kernel<<<NG, 256, MLP_SMEM>>>(x, b11, b12, b21, b22);
    corr_kernel<<<2048, 512, CORR_SMEM>>>();
    gemm1_mma_kernel<<<NG, 256, G1_SMEM>>>(x, ub1);
    finalize_kernel<<<64, 256>>>(g1, be1, ss1, NG);
    gemm2_mma_kernel<<<NG, 256, G2_SMEM>>>(ub2);
    finalize_kernel<<<64, 256>>>(g2, be2, ss2, NG);
    final_kernel<<<16384, 256>>>(x, out);
}